// round 14
// baseline (speedup 1.0000x reference)
#include <cuda_runtime.h>
#include <cuda_bf16.h>
#include <cuda_fp16.h>
#include <math.h>
#include <stdint.h>

// ---------------- problem constants ----------------
#define EMBED_DIM 256
#define N_LEVELS  4
#define N_POINTS  4
#define N_HEADS   8
#define HEAD_DIM  32
#define HMAXC     128
#define WMAXC     128
#define MAX_Q     8192
#define NCH       8          // K=256 / 32
#define EPSV      1e-5f

// valid pixels per batch: 128^2 + 64^2 + 32^2 + 16^2 = 21760
#define PIX_PER_B 21760
#define PIX_TOTAL (2 * PIX_PER_B)
#define CONV_BLOCKS (PIX_TOTAL / 4)   // 4 pixels per 256-thread block

// ---------------- scratch (allocation-free) ----------------
__device__ float    g_off [MAX_Q * EMBED_DIM];
__device__ float    g_aw  [MAX_Q * (N_LEVELS * N_POINTS * N_HEADS)];
__device__ uint32_t g_qA  [2 * NCH * MAX_Q * 16];   // packed query (hi/lo planes)
__device__ uint32_t g_midA[2 * NCH * MAX_Q * 16];   // packed mid
__device__ uint32_t g_Woff [2 * NCH * 256 * 16];
__device__ uint32_t g_Watt [2 * NCH * 128 * 16];
__device__ uint32_t g_Wout [2 * NCH * 256 * 16];
__device__ uint32_t g_Vh  [2 * HMAXC * WMAXC * N_LEVELS * (EMBED_DIM / 2)]; // fp16 V, 67MB

// ---------------- bf16 / fp16 helpers ----------------
__device__ __forceinline__ uint32_t pack_bf16x2(float lo, float hi) {
    uint32_t r;
    asm("cvt.rn.bf16x2.f32 %0, %1, %2;" : "=r"(r) : "f"(hi), "f"(lo));
    return r;
}
__device__ __forceinline__ uint32_t pack_f16x2(float lo, float hi) {
    uint32_t r;
    asm("cvt.rn.f16x2.f32 %0, %1, %2;" : "=r"(r) : "f"(hi), "f"(lo));
    return r;
}
__device__ __forceinline__ float bf16lo_f(uint32_t w) { return __uint_as_float(w << 16); }
__device__ __forceinline__ float bf16hi_f(uint32_t w) { return __uint_as_float(w & 0xffff0000u); }

__device__ __forceinline__ void bf16split2(float x, float y, uint32_t& h, uint32_t& l) {
    h = pack_bf16x2(x, y);
    l = pack_bf16x2(x - bf16lo_f(h), y - bf16hi_f(h));
}

__device__ __forceinline__ void mma_bf16(float* d,
    uint32_t a0, uint32_t a1, uint32_t a2, uint32_t a3,
    uint32_t b0, uint32_t b1) {
    asm volatile(
        "mma.sync.aligned.m16n8k16.row.col.f32.bf16.bf16.f32 "
        "{%0,%1,%2,%3}, {%4,%5,%6,%7}, {%8,%9}, {%0,%1,%2,%3};\n"
        : "+f"(d[0]), "+f"(d[1]), "+f"(d[2]), "+f"(d[3])
        : "r"(a0), "r"(a1), "r"(a2), "r"(a3), "r"(b0), "r"(b1));
}

// step-innermost permutation: kpair kw (0..15) -> (kw&3)*4 + (kw>>3)*2 + ((kw>>2)&1)
__device__ __forceinline__ int widx2(int kw) {
    return (kw & 3) * 4 + (kw >> 3) * 2 + ((kw >> 2) & 1);
}

// ---------------- cp.async (L1-bypass) ----------------
#define CP_ASYNC16(dst, src) \
    asm volatile("cp.async.cg.shared.global [%0], [%1], 16;\n" :: "r"(dst), "l"(src))
#define CP_COMMIT() asm volatile("cp.async.commit_group;\n" ::: "memory")
#define CP_WAIT(n)  asm volatile("cp.async.wait_group %0;\n" :: "n"(n) : "memory")

// ================= V fp32 -> fp16 conversion (valid regions only) =================
// 4 pixels per block (256 threads, 64 threads/pixel, float4 per thread)
__global__ __launch_bounds__(256) void conv_v_kernel(
    const float* __restrict__ V, uint32_t* __restrict__ Vh)
{
    const int tid = threadIdx.x;
    const int pix = blockIdx.x * 4 + (tid >> 6);
    const int t64 = tid & 63;

    int b = (pix >= PIX_PER_B) ? 1 : 0;
    int r = pix - b * PIX_PER_B;
    int l, lg;                         // level, log2(size)
    int idx;
    if (r < 16384)      { l = 0; lg = 7; idx = r; }
    else if (r < 20480) { l = 1; lg = 6; idx = r - 16384; }
    else if (r < 21504) { l = 2; lg = 5; idx = r - 20480; }
    else                { l = 3; lg = 4; idx = r - 21504; }
    int x = idx >> lg;
    int y = idx & ((1 << lg) - 1);

    int base = (((b * HMAXC + x) * WMAXC + y) * N_LEVELS + l) * EMBED_DIM;  // element idx
    float4 v = *(const float4*)(V + base + t64 * 4);
    uint2 o;
    o.x = pack_f16x2(v.x, v.y);
    o.y = pack_f16x2(v.z, v.w);
    *(uint2*)(Vh + (base >> 1) + t64 * 2) = o;
}

// ================= single merged prepack kernel =================
__global__ __launch_bounds__(128) void prepack_all_kernel(
    const float* __restrict__ query,
    const float* __restrict__ W_off, const float* __restrict__ W_attn,
    const float* __restrict__ W_out,
    uint32_t* __restrict__ pq, uint32_t* __restrict__ pwoff,
    uint32_t* __restrict__ pwatt, uint32_t* __restrict__ pwout,
    int Q)
{
    const int ch  = blockIdx.x;
    const int seg = blockIdx.y;
    const int nQseg = Q >> 7;
    const int tid = threadIdx.x;

    uint32_t hw[16], lw[16];

    if (seg < nQseg) {
        const int row = seg * 128 + tid;
        const float* src = query + (size_t)row * (NCH * 32) + ch * 32;
        #pragma unroll
        for (int kw = 0; kw < 16; kw++) {
            float2 v = *(const float2*)(src + 2 * kw);
            int w = widx2(kw);
            bf16split2(v.x, v.y, hw[w], lw[w]);
        }
        size_t base = ((size_t)ch * Q + row) * 16;
        size_t pstr = (size_t)NCH * Q * 16;
        #pragma unroll
        for (int g = 0; g < 4; g++) {
            *(uint4*)&pq[base + g * 4]        = *(uint4*)&hw[g * 4];
            *(uint4*)&pq[pstr + base + g * 4] = *(uint4*)&lw[g * 4];
        }
    } else {
        const int wseg = seg - nQseg;
        const float* B; uint32_t* out; int N; int colOff;
        if (wseg == 0)      { B = W_off;  out = pwoff; N = 256; colOff = 0;   }
        else if (wseg == 1) { B = W_off;  out = pwoff; N = 256; colOff = 128; }
        else if (wseg == 2) { B = W_attn; out = pwatt; N = 128; colOff = 0;   }
        else if (wseg == 3) { B = W_out;  out = pwout; N = 256; colOff = 0;   }
        else                { B = W_out;  out = pwout; N = 256; colOff = 128; }
        const int n = colOff + tid;
        #pragma unroll
        for (int kw = 0; kw < 16; kw++) {
            int k = ch * 32 + 2 * kw;
            float x = B[(size_t)k * N + n];
            float y = B[(size_t)(k + 1) * N + n];
            int w = widx2(kw);
            bf16split2(x, y, hw[w], lw[w]);
        }
        size_t base = ((size_t)ch * N + n) * 16;
        size_t pstr = (size_t)NCH * N * 16;
        #pragma unroll
        for (int g = 0; g < 4; g++) {
            *(uint4*)&out[base + g * 4]        = *(uint4*)&hw[g * 4];
            *(uint4*)&out[pstr + base + g * 4] = *(uint4*)&lw[g * 4];
        }
    }
}

// ================ bf16x3 mma GEMM on prepacked operands ================
#define A_W (128 * 16)             // 2048 words per A plane
#define B_W (64 * 16)              // 1024 words per B plane
#define BUF_W (2 * A_W + 2 * B_W)  // 6144 words per buffer
#define NBUF 4
#define GEMM_SMEM (NBUF * BUF_W * 4)  // 98304 bytes

__global__ __launch_bounds__(256, 2) void gemm_packed_kernel(
    const uint32_t* __restrict__ Ap, int Qrows,
    const uint32_t* __restrict__ Bp0, const float* __restrict__ bias0,
    float* __restrict__ C0, int N0, int nb0,
    const uint32_t* __restrict__ Bp1, const float* __restrict__ bias1,
    float* __restrict__ C1, int N1)
{
    extern __shared__ uint32_t sm[];
    const int tid = threadIdx.x;
    const int lid = tid & 31;
    const int wid = tid >> 5;
    const int rowBase = blockIdx.y * 128;

    const uint32_t* Bp; const float* bias; float* C; int ldN; int colBase;
    if ((int)blockIdx.x < nb0) {
        Bp = Bp0; bias = bias0; C = C0; ldN = N0; colBase = blockIdx.x * 64;
    } else {
        Bp = Bp1; bias = bias1; C = C1; ldN = N1; colBase = (blockIdx.x - nb0) * 64;
    }

    const size_t Astr = (size_t)NCH * Qrows * 16;
    const size_t Bstr = (size_t)NCH * ldN * 16;
    const size_t dA   = (size_t)Qrows * 16;
    const size_t dB   = (size_t)ldN * 16;

    const int mOff = (wid >> 1) * 32;
    const int nOff = (wid & 1) * 32;
    const int gq = lid >> 2;
    const int tq = lid & 3;

    const uint32_t* aP[4]; uint32_t aD[4];
    const uint32_t* bP[2]; uint32_t bD[2];
    #pragma unroll
    for (int i = 0; i < 4; i++) {
        int s = tid + i * 256, pl = s >> 9, rem = s & 511;
        aP[i] = Ap + (size_t)pl * Astr + (size_t)rowBase * 16 + rem * 4;
        aD[i] = pl * A_W + rem * 4;
    }
    #pragma unroll
    for (int i = 0; i < 2; i++) {
        int s = tid + i * 256, pl = s >> 8, rem = s & 255;
        bP[i] = Bp + (size_t)pl * Bstr + (size_t)colBase * 16 + rem * 4;
        bD[i] = 2 * A_W + pl * B_W + rem * 4;
    }
    uint32_t sbase[NBUF];
    #pragma unroll
    for (int b = 0; b < NBUF; b++)
        sbase[b] = (uint32_t)__cvta_generic_to_shared(sm + b * BUF_W);

    float acc[2][4][4];
    #pragma unroll
    for (int mt = 0; mt < 2; mt++)
        #pragma unroll
        for (int nt = 0; nt < 4; nt++)
            #pragma unroll
            for (int j = 0; j < 4; j++)
                acc[mt][nt][j] = 0.0f;

    auto issue = [&](int ch) {
        uint32_t sb = sbase[ch & (NBUF - 1)];
        size_t oA = ch * dA, oB = ch * dB;
        #pragma unroll
        for (int i = 0; i < 4; i++)
            CP_ASYNC16(sb + (aD[i] << 2), aP[i] + oA);
        #pragma unroll
        for (int i = 0; i < 2; i++)
            CP_ASYNC16(sb + (bD[i] << 2), bP[i] + oB);
        CP_COMMIT();
    };

    issue(0);
    issue(1);

    for (int ch = 0; ch < NCH; ch++) {
        if (ch + 2 < NCH) { issue(ch + 2); CP_WAIT(2); }
        else if (ch + 1 < NCH) { CP_WAIT(1); }
        else { CP_WAIT(0); }
        __syncthreads();

        const uint32_t* bAh = sm + (ch & (NBUF - 1)) * BUF_W;
        const uint32_t* bAl = bAh + A_W;
        const uint32_t* bBh = bAh + 2 * A_W;
        const uint32_t* bBl = bBh + B_W;

        uint4 PAh[2], QAh[2], PAl[2], QAl[2];
        uint4 BH[4], BL[4];
        #pragma unroll
        for (int mt = 0; mt < 2; mt++) {
            int row = mOff + mt * 16 + gq;
            PAh[mt] = *(const uint4*)&bAh[row * 16 + tq * 4];
            QAh[mt] = *(const uint4*)&bAh[(row + 8) * 16 + tq * 4];
            PAl[mt] = *(const uint4*)&bAl[row * 16 + tq * 4];
            QAl[mt] = *(const uint4*)&bAl[(row + 8) * 16 + tq * 4];
        }
        #pragma unroll
        for (int nt = 0; nt < 4; nt++) {
            int col = nOff + nt * 8 + gq;
            BH[nt] = *(const uint4*)&bBh[col * 16 + tq * 4];
            BL[nt] = *(const uint4*)&bBl[col * 16 + tq * 4];
        }

        #pragma unroll
        for (int mt = 0; mt < 2; mt++)
            #pragma unroll
            for (int nt = 0; nt < 4; nt++) {
                mma_bf16(acc[mt][nt], PAh[mt].x, QAh[mt].x, PAh[mt].y, QAh[mt].y,
                         BH[nt].x, BH[nt].y);
                mma_bf16(acc[mt][nt], PAl[mt].x, QAl[mt].x, PAl[mt].y, QAl[mt].y,
                         BH[nt].x, BH[nt].y);
                mma_bf16(acc[mt][nt], PAh[mt].x, QAh[mt].x, PAh[mt].y, QAh[mt].y,
                         BL[nt].x, BL[nt].y);
                mma_bf16(acc[mt][nt], PAh[mt].z, QAh[mt].z, PAh[mt].w, QAh[mt].w,
                         BH[nt].z, BH[nt].w);
                mma_bf16(acc[mt][nt], PAl[mt].z, QAl[mt].z, PAl[mt].w, QAl[mt].w,
                         BH[nt].z, BH[nt].w);
                mma_bf16(acc[mt][nt], PAh[mt].z, QAh[mt].z, PAh[mt].w, QAh[mt].w,
                         BL[nt].z, BL[nt].w);
            }
    }

    #pragma unroll
    for (int mt = 0; mt < 2; mt++) {
        int row = rowBase + mOff + mt * 16 + gq;
        #pragma unroll
        for (int nt = 0; nt < 4; nt++) {
            int col = colBase + nOff + nt * 8 + 2 * tq;
            float2 bs = *(const float2*)(bias + col);
            float2 v0, v1;
            v0.x = acc[mt][nt][0] + bs.x;
            v0.y = acc[mt][nt][1] + bs.y;
            v1.x = acc[mt][nt][2] + bs.x;
            v1.y = acc[mt][nt][3] + bs.y;
            *(float2*)(C + (size_t)row * ldN + col) = v0;
            *(float2*)(C + (size_t)(row + 8) * ldN + col) = v1;
        }
    }
}

// ---------------- sampling kernel: softmax + fp16 bilinear gather ----------------
// 2 queries/block, 512 threads. Warp=(sub,h); lanes 0-15 corners {00,01},
// lanes 16-31 corners {10,11}; each lane gathers half2 (2 dims).
__global__ __launch_bounds__(512) void msda_sample_kernel(
    const float* __restrict__ off,
    const float* __restrict__ awr,
    const float* __restrict__ xyref,
    const uint32_t* __restrict__ Vh,
    const int*   __restrict__ batch_offsets,
    const int*   __restrict__ spatial_shapes,
    uint32_t* __restrict__ midp,
    int Q)
{
    const int tid  = threadIdx.x;
    const int sub  = tid >> 8;
    const int stid = tid & 255;
    const int q    = blockIdx.x * 2 + sub;

    __shared__ float4 s_w[2][16][8];
    __shared__ int4   s_b[2][16][8];
    __shared__ float  s_e[2][16][8];
    __shared__ float  s_inv[2][8];

    if (stid < 128) {
        s_e[sub][stid >> 3][stid & 7] = awr[(long)q * 128 + stid];
    }
    __syncthreads();

    if (stid < 8) {
        float m = -1e30f;
        #pragma unroll
        for (int lp = 0; lp < 16; lp++) m = fmaxf(m, s_e[sub][lp][stid]);
        float s = 0.0f;
        #pragma unroll
        for (int lp = 0; lp < 16; lp++) {
            float e = __expf(s_e[sub][lp][stid] - m);
            s_e[sub][lp][stid] = e;
            s += e;
        }
        s_inv[sub][stid] = 1.0f / s;
    }
    __syncthreads();

    if (stid < 128) {
        const int lp = stid >> 3;
        const int h  = stid & 7;
        const int l  = lp >> 2;

        const int   wi  = spatial_shapes[l * 2 + 1];
        const int   hi  = spatial_shapes[l * 2 + 0];
        const float wsz = (float)wi;
        const float hsz = (float)hi;
        const int   wcap = wi - 1;
        const int   hcap = hi - 1;

        float rx = fminf(fmaxf(xyref[(long)q * 2 + 0], 0.0f), 1.0f);
        float ry = fminf(fmaxf(xyref[(long)q * 2 + 1], 0.0f), 1.0f);
        float invx = __logf(fminf(fmaxf(rx, EPSV), 1.0f) / fminf(fmaxf(1.0f - rx, EPSV), 1.0f));
        float invy = __logf(fminf(fmaxf(ry, EPSV), 1.0f) / fminf(fmaxf(1.0f - ry, EPSV), 1.0f));

        float ox = off[(long)q * 256 + lp * 16 + h * 2 + 0];
        float oy = off[(long)q * 256 + lp * 16 + h * 2 + 1];

        float sx = 1.0f / (1.0f + __expf(-(invx + ox)));
        float sy = 1.0f / (1.0f + __expf(-(invy + oy)));
        float locx = sx * 2.0f - 1.0f;
        float locy = sy * 2.0f - 1.0f;
        // NB: reference pairs loc[...,0] with w_sz and uses x as the FIRST
        // spatial index (H axis). Replicate exactly.
        float x = ((locx + 1.0f) * wsz - 1.0f) * 0.5f;
        float y = ((locy + 1.0f) * hsz - 1.0f) * 0.5f;

        int x0 = (int)floorf(x);
        int y0 = (int)floorf(y);
        int x1c = min(max(x0 + 1, 0), wcap);
        int x0c = min(max(x0,     0), wcap);
        int y1c = min(max(y0 + 1, 0), hcap);
        int y0c = min(max(y0,     0), hcap);

        float x0f = (float)x0c, x1f = (float)x1c;
        float y0f = (float)y0c, y1f = (float)y1c;
        float wa = (x1f - x) * (y1f - y);
        float wb = (x1f - x) * (y - y0f);
        float wc = (x - x0f) * (y1f - y);
        float wd = (x - x0f) * (y - y0f);

        float aw = s_e[sub][lp][h] * s_inv[sub][h];

        int b  = (q >= batch_offsets[1]) ? 1 : 0;
        int bb = b * HMAXC;
        int hd = h * HEAD_DIM;
        int base00 = (((bb + x0c) * WMAXC + y0c) * N_LEVELS + l) * EMBED_DIM + hd;
        int base01 = (((bb + x0c) * WMAXC + y1c) * N_LEVELS + l) * EMBED_DIM + hd;
        int base10 = (((bb + x1c) * WMAXC + y0c) * N_LEVELS + l) * EMBED_DIM + hd;
        int base11 = (((bb + x1c) * WMAXC + y1c) * N_LEVELS + l) * EMBED_DIM + hd;

        s_w[sub][lp][h] = make_float4(wa * aw, wb * aw, wc * aw, wd * aw);
        s_b[sub][lp][h] = make_int4(base00, base01, base10, base11);
    }
    __syncthreads();

    const int h    = (stid >> 5) & 7;
    const int lidw = stid & 31;
    const int c2   = lidw >> 4;          // 0: corners {00,01}; 1: corners {10,11}
    const int dd   = (lidw & 15) * 2;    // dim pair within head

    float accx = 0.0f, accy = 0.0f;
    #pragma unroll 4
    for (int lp = 0; lp < 16; lp++) {
        float4 wts = s_w[sub][lp][h];
        int4   bs  = s_b[sub][lp][h];
        int  bA = c2 ? bs.z : bs.x;
        int  bB = c2 ? bs.w : bs.y;
        float wA = c2 ? wts.z : wts.x;
        float wB = c2 ? wts.w : wts.y;
        uint32_t pA = Vh[(bA + dd) >> 1];
        uint32_t pB = Vh[(bB + dd) >> 1];
        float2 vA = __half22float2(*(__half2*)&pA);
        float2 vB = __half22float2(*(__half2*)&pB);
        accx = fmaf(wA, vA.x, fmaf(wB, vB.x, accx));
        accy = fmaf(wA, vA.y, fmaf(wB, vB.y, accy));
    }
    // combine the two corner-halves across half-warps
    accx += __shfl_xor_sync(0xffffffffu, accx, 16);
    accy += __shfl_xor_sync(0xffffffffu, accy, 16);

    if (c2 == 0) {
        uint32_t hw, lw;
        bf16split2(accx, accy, hw, lw);
        int kp = h * 16 + (lidw & 15);      // k-pair index (dims 2kp, 2kp+1)
        int ch = kp >> 4;
        int w  = widx2(kp & 15);
        size_t base = ((size_t)ch * Q + q) * 16 + w;
        size_t pstr = (size_t)NCH * Q * 16;
        midp[base]        = hw;
        midp[pstr + base] = lw;
    }
}

// ---------------- launch ----------------
extern "C" void kernel_launch(void* const* d_in, const int* in_sizes, int n_in,
                              void* d_out, int out_size)
{
    const float* query  = (const float*)d_in[0];
    const float* xyref  = (const float*)d_in[1];
    const float* V      = (const float*)d_in[2];
    const float* W_off  = (const float*)d_in[3];
    const float* b_off  = (const float*)d_in[4];
    const float* W_attn = (const float*)d_in[5];
    const float* b_attn = (const float*)d_in[6];
    const float* W_out  = (const float*)d_in[7];
    const float* b_out  = (const float*)d_in[8];
    const int* batch_offsets  = (const int*)d_in[9];
    const int* spatial_shapes = (const int*)d_in[10];
    float* out = (float*)d_out;

    const int Q = in_sizes[0] / EMBED_DIM;

    float *p_off, *p_aw;
    uint32_t *p_qA, *p_midA, *p_Woff, *p_Watt, *p_Wout, *p_Vh;
    cudaGetSymbolAddress((void**)&p_off,  g_off);
    cudaGetSymbolAddress((void**)&p_aw,   g_aw);
    cudaGetSymbolAddress((void**)&p_qA,   g_qA);
    cudaGetSymbolAddress((void**)&p_midA, g_midA);
    cudaGetSymbolAddress((void**)&p_Woff, g_Woff);
    cudaGetSymbolAddress((void**)&p_Watt, g_Watt);
    cudaGetSymbolAddress((void**)&p_Wout, g_Wout);
    cudaGetSymbolAddress((void**)&p_Vh,   g_Vh);

    cudaFuncSetAttribute(gemm_packed_kernel,
                         cudaFuncAttributeMaxDynamicSharedMemorySize, GEMM_SMEM);

    // V fp32 -> fp16 (valid level regions only)
    conv_v_kernel<<<CONV_BLOCKS, 256>>>(V, p_Vh);

    // single merged prepack: query + all 3 weight matrices
    prepack_all_kernel<<<dim3(NCH, Q / 128 + 5), 128>>>(
        query, W_off, W_attn, W_out,
        p_qA, p_Woff, p_Watt, p_Wout, Q);

    // fused GEMM1: off (4 col-blocks of 64) + aw (2 col-blocks of 64)
    gemm_packed_kernel<<<dim3(6, Q / 128), 256, GEMM_SMEM>>>(
        p_qA, Q,
        p_Woff, b_off, p_off, EMBED_DIM, 4,
        p_Watt, b_attn, p_aw, 128);

    // softmax + deformable sampling (fp16 gather) -> packed mid
    msda_sample_kernel<<<Q / 2, 512>>>(
        p_off, p_aw, xyref, p_Vh, batch_offsets, spatial_shapes, p_midA, Q);

    // GEMM2: out = mid @ W_out + b_out (4 col-blocks of 64)
    gemm_packed_kernel<<<dim3(4, Q / 128), 256, GEMM_SMEM>>>(
        p_midA, Q,
        p_Wout, b_out, out, EMBED_DIM, 4,
        nullptr, nullptr, nullptr, 128);
}

// round 15
// speedup vs baseline: 1.0649x; 1.0649x over previous
#include <cuda_runtime.h>
#include <cuda_bf16.h>
#include <cuda_fp16.h>
#include <math.h>
#include <stdint.h>

// ---------------- problem constants ----------------
#define EMBED_DIM 256
#define N_LEVELS  4
#define N_POINTS  4
#define N_HEADS   8
#define HEAD_DIM  32
#define HMAXC     128
#define WMAXC     128
#define MAX_Q     8192
#define NCH       8          // K=256 / 32
#define EPSV      1e-5f

// valid pixels per batch: 128^2 + 64^2 + 32^2 + 16^2 = 21760
#define PIX_PER_B 21760
#define PIX_TOTAL (2 * PIX_PER_B)
#define CONV_BLOCKS (PIX_TOTAL / 4)   // 4 pixels per 256-thread block

// ---------------- scratch (allocation-free) ----------------
__device__ float    g_off [MAX_Q * EMBED_DIM];
__device__ float    g_aw  [MAX_Q * (N_LEVELS * N_POINTS * N_HEADS)];
__device__ uint32_t g_qA  [2 * NCH * MAX_Q * 16];   // packed query (hi/lo planes)
__device__ uint32_t g_midA[2 * NCH * MAX_Q * 16];   // packed mid
__device__ uint32_t g_Woff [2 * NCH * 256 * 16];
__device__ uint32_t g_Watt [2 * NCH * 128 * 16];
__device__ uint32_t g_Wout [2 * NCH * 256 * 16];
__device__ uint32_t g_Vh  [2 * HMAXC * WMAXC * N_LEVELS * (EMBED_DIM / 2)]; // fp16 V, 67MB

// ---------------- bf16 / fp16 helpers ----------------
__device__ __forceinline__ uint32_t pack_bf16x2(float lo, float hi) {
    uint32_t r;
    asm("cvt.rn.bf16x2.f32 %0, %1, %2;" : "=r"(r) : "f"(hi), "f"(lo));
    return r;
}
__device__ __forceinline__ uint32_t pack_f16x2(float lo, float hi) {
    uint32_t r;
    asm("cvt.rn.f16x2.f32 %0, %1, %2;" : "=r"(r) : "f"(hi), "f"(lo));
    return r;
}
__device__ __forceinline__ float bf16lo_f(uint32_t w) { return __uint_as_float(w << 16); }
__device__ __forceinline__ float bf16hi_f(uint32_t w) { return __uint_as_float(w & 0xffff0000u); }

__device__ __forceinline__ void bf16split2(float x, float y, uint32_t& h, uint32_t& l) {
    h = pack_bf16x2(x, y);
    l = pack_bf16x2(x - bf16lo_f(h), y - bf16hi_f(h));
}

__device__ __forceinline__ void mma_bf16(float* d,
    uint32_t a0, uint32_t a1, uint32_t a2, uint32_t a3,
    uint32_t b0, uint32_t b1) {
    asm volatile(
        "mma.sync.aligned.m16n8k16.row.col.f32.bf16.bf16.f32 "
        "{%0,%1,%2,%3}, {%4,%5,%6,%7}, {%8,%9}, {%0,%1,%2,%3};\n"
        : "+f"(d[0]), "+f"(d[1]), "+f"(d[2]), "+f"(d[3])
        : "r"(a0), "r"(a1), "r"(a2), "r"(a3), "r"(b0), "r"(b1));
}

// step-innermost permutation: kpair kw (0..15) -> (kw&3)*4 + (kw>>3)*2 + ((kw>>2)&1)
__device__ __forceinline__ int widx2(int kw) {
    return (kw & 3) * 4 + (kw >> 3) * 2 + ((kw >> 2) & 1);
}

// ---------------- cp.async (L1-bypass) ----------------
#define CP_ASYNC16(dst, src) \
    asm volatile("cp.async.cg.shared.global [%0], [%1], 16;\n" :: "r"(dst), "l"(src))
#define CP_COMMIT() asm volatile("cp.async.commit_group;\n" ::: "memory")
#define CP_WAIT(n)  asm volatile("cp.async.wait_group %0;\n" :: "n"(n) : "memory")

// ================= V fp32 -> fp16 conversion (valid regions only) =================
__global__ __launch_bounds__(256) void conv_v_kernel(
    const float* __restrict__ V, uint32_t* __restrict__ Vh)
{
    const int tid = threadIdx.x;
    const int pix = blockIdx.x * 4 + (tid >> 6);
    const int t64 = tid & 63;

    int b = (pix >= PIX_PER_B) ? 1 : 0;
    int r = pix - b * PIX_PER_B;
    int l, lg;
    int idx;
    if (r < 16384)      { l = 0; lg = 7; idx = r; }
    else if (r < 20480) { l = 1; lg = 6; idx = r - 16384; }
    else if (r < 21504) { l = 2; lg = 5; idx = r - 20480; }
    else                { l = 3; lg = 4; idx = r - 21504; }
    int x = idx >> lg;
    int y = idx & ((1 << lg) - 1);

    int base = (((b * HMAXC + x) * WMAXC + y) * N_LEVELS + l) * EMBED_DIM;
    float4 v = *(const float4*)(V + base + t64 * 4);
    uint2 o;
    o.x = pack_f16x2(v.x, v.y);
    o.y = pack_f16x2(v.z, v.w);
    *(uint2*)(Vh + (base >> 1) + t64 * 2) = o;
}

// ================= single merged prepack kernel =================
__global__ __launch_bounds__(128) void prepack_all_kernel(
    const float* __restrict__ query,
    const float* __restrict__ W_off, const float* __restrict__ W_attn,
    const float* __restrict__ W_out,
    uint32_t* __restrict__ pq, uint32_t* __restrict__ pwoff,
    uint32_t* __restrict__ pwatt, uint32_t* __restrict__ pwout,
    int Q)
{
    const int ch  = blockIdx.x;
    const int seg = blockIdx.y;
    const int nQseg = Q >> 7;
    const int tid = threadIdx.x;

    uint32_t hw[16], lw[16];

    if (seg < nQseg) {
        const int row = seg * 128 + tid;
        const float* src = query + (size_t)row * (NCH * 32) + ch * 32;
        #pragma unroll
        for (int kw = 0; kw < 16; kw++) {
            float2 v = *(const float2*)(src + 2 * kw);
            int w = widx2(kw);
            bf16split2(v.x, v.y, hw[w], lw[w]);
        }
        size_t base = ((size_t)ch * Q + row) * 16;
        size_t pstr = (size_t)NCH * Q * 16;
        #pragma unroll
        for (int g = 0; g < 4; g++) {
            *(uint4*)&pq[base + g * 4]        = *(uint4*)&hw[g * 4];
            *(uint4*)&pq[pstr + base + g * 4] = *(uint4*)&lw[g * 4];
        }
    } else {
        const int wseg = seg - nQseg;
        const float* B; uint32_t* out; int N; int colOff;
        if (wseg == 0)      { B = W_off;  out = pwoff; N = 256; colOff = 0;   }
        else if (wseg == 1) { B = W_off;  out = pwoff; N = 256; colOff = 128; }
        else if (wseg == 2) { B = W_attn; out = pwatt; N = 128; colOff = 0;   }
        else if (wseg == 3) { B = W_out;  out = pwout; N = 256; colOff = 0;   }
        else                { B = W_out;  out = pwout; N = 256; colOff = 128; }
        const int n = colOff + tid;
        #pragma unroll
        for (int kw = 0; kw < 16; kw++) {
            int k = ch * 32 + 2 * kw;
            float x = B[(size_t)k * N + n];
            float y = B[(size_t)(k + 1) * N + n];
            int w = widx2(kw);
            bf16split2(x, y, hw[w], lw[w]);
        }
        size_t base = ((size_t)ch * N + n) * 16;
        size_t pstr = (size_t)NCH * N * 16;
        #pragma unroll
        for (int g = 0; g < 4; g++) {
            *(uint4*)&out[base + g * 4]        = *(uint4*)&hw[g * 4];
            *(uint4*)&out[pstr + base + g * 4] = *(uint4*)&lw[g * 4];
        }
    }
}

// ================ bf16x3 mma GEMM on prepacked operands ================
#define A_W (128 * 16)             // 2048 words per A plane
#define B_W (64 * 16)              // 1024 words per B plane
#define BUF_W (2 * A_W + 2 * B_W)  // 6144 words per buffer
#define NBUF 4
#define GEMM_SMEM (NBUF * BUF_W * 4)  // 98304 bytes

__global__ __launch_bounds__(256, 2) void gemm_packed_kernel(
    const uint32_t* __restrict__ Ap, int Qrows,
    const uint32_t* __restrict__ Bp0, const float* __restrict__ bias0,
    float* __restrict__ C0, int N0, int nb0,
    const uint32_t* __restrict__ Bp1, const float* __restrict__ bias1,
    float* __restrict__ C1, int N1)
{
    extern __shared__ uint32_t sm[];
    const int tid = threadIdx.x;
    const int lid = tid & 31;
    const int wid = tid >> 5;
    const int rowBase = blockIdx.y * 128;

    const uint32_t* Bp; const float* bias; float* C; int ldN; int colBase;
    if ((int)blockIdx.x < nb0) {
        Bp = Bp0; bias = bias0; C = C0; ldN = N0; colBase = blockIdx.x * 64;
    } else {
        Bp = Bp1; bias = bias1; C = C1; ldN = N1; colBase = (blockIdx.x - nb0) * 64;
    }

    const size_t Astr = (size_t)NCH * Qrows * 16;
    const size_t Bstr = (size_t)NCH * ldN * 16;
    const size_t dA   = (size_t)Qrows * 16;
    const size_t dB   = (size_t)ldN * 16;

    const int mOff = (wid >> 1) * 32;
    const int nOff = (wid & 1) * 32;
    const int gq = lid >> 2;
    const int tq = lid & 3;

    const uint32_t* aP[4]; uint32_t aD[4];
    const uint32_t* bP[2]; uint32_t bD[2];
    #pragma unroll
    for (int i = 0; i < 4; i++) {
        int s = tid + i * 256, pl = s >> 9, rem = s & 511;
        aP[i] = Ap + (size_t)pl * Astr + (size_t)rowBase * 16 + rem * 4;
        aD[i] = pl * A_W + rem * 4;
    }
    #pragma unroll
    for (int i = 0; i < 2; i++) {
        int s = tid + i * 256, pl = s >> 8, rem = s & 255;
        bP[i] = Bp + (size_t)pl * Bstr + (size_t)colBase * 16 + rem * 4;
        bD[i] = 2 * A_W + pl * B_W + rem * 4;
    }
    uint32_t sbase[NBUF];
    #pragma unroll
    for (int b = 0; b < NBUF; b++)
        sbase[b] = (uint32_t)__cvta_generic_to_shared(sm + b * BUF_W);

    float acc[2][4][4];
    #pragma unroll
    for (int mt = 0; mt < 2; mt++)
        #pragma unroll
        for (int nt = 0; nt < 4; nt++)
            #pragma unroll
            for (int j = 0; j < 4; j++)
                acc[mt][nt][j] = 0.0f;

    auto issue = [&](int ch) {
        uint32_t sb = sbase[ch & (NBUF - 1)];
        size_t oA = ch * dA, oB = ch * dB;
        #pragma unroll
        for (int i = 0; i < 4; i++)
            CP_ASYNC16(sb + (aD[i] << 2), aP[i] + oA);
        #pragma unroll
        for (int i = 0; i < 2; i++)
            CP_ASYNC16(sb + (bD[i] << 2), bP[i] + oB);
        CP_COMMIT();
    };

    issue(0);
    issue(1);

    for (int ch = 0; ch < NCH; ch++) {
        if (ch + 2 < NCH) { issue(ch + 2); CP_WAIT(2); }
        else if (ch + 1 < NCH) { CP_WAIT(1); }
        else { CP_WAIT(0); }
        __syncthreads();

        const uint32_t* bAh = sm + (ch & (NBUF - 1)) * BUF_W;
        const uint32_t* bAl = bAh + A_W;
        const uint32_t* bBh = bAh + 2 * A_W;
        const uint32_t* bBl = bBh + B_W;

        uint4 PAh[2], QAh[2], PAl[2], QAl[2];
        uint4 BH[4], BL[4];
        #pragma unroll
        for (int mt = 0; mt < 2; mt++) {
            int row = mOff + mt * 16 + gq;
            PAh[mt] = *(const uint4*)&bAh[row * 16 + tq * 4];
            QAh[mt] = *(const uint4*)&bAh[(row + 8) * 16 + tq * 4];
            PAl[mt] = *(const uint4*)&bAl[row * 16 + tq * 4];
            QAl[mt] = *(const uint4*)&bAl[(row + 8) * 16 + tq * 4];
        }
        #pragma unroll
        for (int nt = 0; nt < 4; nt++) {
            int col = nOff + nt * 8 + gq;
            BH[nt] = *(const uint4*)&bBh[col * 16 + tq * 4];
            BL[nt] = *(const uint4*)&bBl[col * 16 + tq * 4];
        }

        #pragma unroll
        for (int mt = 0; mt < 2; mt++)
            #pragma unroll
            for (int nt = 0; nt < 4; nt++) {
                mma_bf16(acc[mt][nt], PAh[mt].x, QAh[mt].x, PAh[mt].y, QAh[mt].y,
                         BH[nt].x, BH[nt].y);
                mma_bf16(acc[mt][nt], PAl[mt].x, QAl[mt].x, PAl[mt].y, QAl[mt].y,
                         BH[nt].x, BH[nt].y);
                mma_bf16(acc[mt][nt], PAh[mt].x, QAh[mt].x, PAh[mt].y, QAh[mt].y,
                         BL[nt].x, BL[nt].y);
                mma_bf16(acc[mt][nt], PAh[mt].z, QAh[mt].z, PAh[mt].w, QAh[mt].w,
                         BH[nt].z, BH[nt].w);
                mma_bf16(acc[mt][nt], PAl[mt].z, QAl[mt].z, PAl[mt].w, QAl[mt].w,
                         BH[nt].z, BH[nt].w);
                mma_bf16(acc[mt][nt], PAh[mt].z, QAh[mt].z, PAh[mt].w, QAh[mt].w,
                         BL[nt].z, BL[nt].w);
            }
    }

    #pragma unroll
    for (int mt = 0; mt < 2; mt++) {
        int row = rowBase + mOff + mt * 16 + gq;
        #pragma unroll
        for (int nt = 0; nt < 4; nt++) {
            int col = colBase + nOff + nt * 8 + 2 * tq;
            float2 bs = *(const float2*)(bias + col);
            float2 v0, v1;
            v0.x = acc[mt][nt][0] + bs.x;
            v0.y = acc[mt][nt][1] + bs.y;
            v1.x = acc[mt][nt][2] + bs.x;
            v1.y = acc[mt][nt][3] + bs.y;
            *(float2*)(C + (size_t)row * ldN + col) = v0;
            *(float2*)(C + (size_t)(row + 8) * ldN + col) = v1;
        }
    }
}

// ---------------- sampling kernel v3: corner-unrolled fp16 gather ----------------
// 2 queries/block, 512 threads. Warp=(sub,h). Lane = (p=lp parity, c=corner,
// g=dim group): one LDG.128 (8 dims) per lane per iteration, 8 iterations.
__global__ __launch_bounds__(512) void msda_sample_kernel(
    const float* __restrict__ off,
    const float* __restrict__ awr,
    const float* __restrict__ xyref,
    const uint32_t* __restrict__ Vh,
    const int*   __restrict__ batch_offsets,
    const int*   __restrict__ spatial_shapes,
    uint32_t* __restrict__ midp,
    int Q)
{
    const int tid  = threadIdx.x;
    const int sub  = tid >> 8;
    const int stid = tid & 255;
    const int q    = blockIdx.x * 2 + sub;

    // corner-separated: [lp*36 + h*4 + c]; stride 36 -> conflict-free loop LDS
    __shared__ float s_wc[2][16 * 36];
    __shared__ int   s_bc[2][16 * 36];
    __shared__ float s_e[2][16][8];
    __shared__ float s_inv[2][8];

    if (stid < 128) {
        s_e[sub][stid >> 3][stid & 7] = awr[(long)q * 128 + stid];
    }
    __syncthreads();

    if (stid < 8) {
        float m = -1e30f;
        #pragma unroll
        for (int lp = 0; lp < 16; lp++) m = fmaxf(m, s_e[sub][lp][stid]);
        float s = 0.0f;
        #pragma unroll
        for (int lp = 0; lp < 16; lp++) {
            float e = __expf(s_e[sub][lp][stid] - m);
            s_e[sub][lp][stid] = e;
            s += e;
        }
        s_inv[sub][stid] = 1.0f / s;
    }
    __syncthreads();

    if (stid < 128) {
        const int lp = stid >> 3;
        const int h  = stid & 7;
        const int l  = lp >> 2;

        const int   wi  = spatial_shapes[l * 2 + 1];
        const int   hi  = spatial_shapes[l * 2 + 0];
        const float wsz = (float)wi;
        const float hsz = (float)hi;
        const int   wcap = wi - 1;
        const int   hcap = hi - 1;

        float rx = fminf(fmaxf(xyref[(long)q * 2 + 0], 0.0f), 1.0f);
        float ry = fminf(fmaxf(xyref[(long)q * 2 + 1], 0.0f), 1.0f);
        float invx = __logf(fminf(fmaxf(rx, EPSV), 1.0f) / fminf(fmaxf(1.0f - rx, EPSV), 1.0f));
        float invy = __logf(fminf(fmaxf(ry, EPSV), 1.0f) / fminf(fmaxf(1.0f - ry, EPSV), 1.0f));

        float ox = off[(long)q * 256 + lp * 16 + h * 2 + 0];
        float oy = off[(long)q * 256 + lp * 16 + h * 2 + 1];

        float sx = 1.0f / (1.0f + __expf(-(invx + ox)));
        float sy = 1.0f / (1.0f + __expf(-(invy + oy)));
        float locx = sx * 2.0f - 1.0f;
        float locy = sy * 2.0f - 1.0f;
        // NB: reference pairs loc[...,0] with w_sz and uses x as the FIRST
        // spatial index (H axis). Replicate exactly.
        float x = ((locx + 1.0f) * wsz - 1.0f) * 0.5f;
        float y = ((locy + 1.0f) * hsz - 1.0f) * 0.5f;

        int x0 = (int)floorf(x);
        int y0 = (int)floorf(y);
        int x1c = min(max(x0 + 1, 0), wcap);
        int x0c = min(max(x0,     0), wcap);
        int y1c = min(max(y0 + 1, 0), hcap);
        int y0c = min(max(y0,     0), hcap);

        float x0f = (float)x0c, x1f = (float)x1c;
        float y0f = (float)y0c, y1f = (float)y1c;
        float wa = (x1f - x) * (y1f - y);
        float wb = (x1f - x) * (y - y0f);
        float wc = (x - x0f) * (y1f - y);
        float wd = (x - x0f) * (y - y0f);

        float aw = s_e[sub][lp][h] * s_inv[sub][h];

        int b  = (q >= batch_offsets[1]) ? 1 : 0;
        int bb = b * HMAXC;
        int hd = h * HEAD_DIM;
        int base00 = (((bb + x0c) * WMAXC + y0c) * N_LEVELS + l) * EMBED_DIM + hd;
        int base01 = (((bb + x0c) * WMAXC + y1c) * N_LEVELS + l) * EMBED_DIM + hd;
        int base10 = (((bb + x1c) * WMAXC + y0c) * N_LEVELS + l) * EMBED_DIM + hd;
        int base11 = (((bb + x1c) * WMAXC + y1c) * N_LEVELS + l) * EMBED_DIM + hd;

        const int o = lp * 36 + h * 4;
        float4 wv = make_float4(wa * aw, wb * aw, wc * aw, wd * aw);
        int4   bv = make_int4(base00 >> 1, base01 >> 1, base10 >> 1, base11 >> 1);
        *(float4*)&s_wc[sub][o] = wv;
        *(int4*)&s_bc[sub][o]   = bv;
    }
    __syncthreads();

    const int h   = (stid >> 5) & 7;
    const int lid = stid & 31;
    const int g   = lid & 3;            // dim group: dims 8g..8g+7
    const int ob  = ((lid >> 4) & 1) * 36 + h * 4 + ((lid >> 2) & 3); // p*36+h*4+c
    const float* wbase = &s_wc[sub][ob];
    const int*   bbase = &s_bc[sub][ob];
    const uint32_t* pV = Vh + g * 4;

    float acc[8];
    #pragma unroll
    for (int j = 0; j < 8; j++) acc[j] = 0.0f;

    #pragma unroll
    for (int it = 0; it < 8; it++) {
        float w = wbase[it * 72];
        int   b = bbase[it * 72];
        uint4 v = *(const uint4*)(pV + b);
        float2 f0 = __half22float2(*(__half2*)&v.x);
        float2 f1 = __half22float2(*(__half2*)&v.y);
        float2 f2 = __half22float2(*(__half2*)&v.z);
        float2 f3 = __half22float2(*(__half2*)&v.w);
        acc[0] = fmaf(w, f0.x, acc[0]);
        acc[1] = fmaf(w, f0.y, acc[1]);
        acc[2] = fmaf(w, f1.x, acc[2]);
        acc[3] = fmaf(w, f1.y, acc[3]);
        acc[4] = fmaf(w, f2.x, acc[4]);
        acc[5] = fmaf(w, f2.y, acc[5]);
        acc[6] = fmaf(w, f3.x, acc[6]);
        acc[7] = fmaf(w, f3.y, acc[7]);
    }

    // reduce over corners (bits 2,3) and lp parity (bit 4)
    #pragma unroll
    for (int j = 0; j < 8; j++) acc[j] += __shfl_xor_sync(0xffffffffu, acc[j], 4);
    #pragma unroll
    for (int j = 0; j < 8; j++) acc[j] += __shfl_xor_sync(0xffffffffu, acc[j], 8);
    #pragma unroll
    for (int j = 0; j < 8; j++) acc[j] += __shfl_xor_sync(0xffffffffu, acc[j], 16);

    if (lid < 4) {   // c==0, p==0, g = lid: owns dims 8*lid .. 8*lid+7
        size_t pstr = (size_t)NCH * Q * 16;
        size_t qb   = ((size_t)h * Q + q) * 16;   // ch == h for these kpairs
        #pragma unroll
        for (int j = 0; j < 4; j++) {
            uint32_t hw, lw;
            bf16split2(acc[2 * j], acc[2 * j + 1], hw, lw);
            int w = widx2(lid * 4 + j);
            midp[qb + w]        = hw;
            midp[pstr + qb + w] = lw;
        }
    }
}

// ---------------- launch ----------------
extern "C" void kernel_launch(void* const* d_in, const int* in_sizes, int n_in,
                              void* d_out, int out_size)
{
    const float* query  = (const float*)d_in[0];
    const float* xyref  = (const float*)d_in[1];
    const float* V      = (const float*)d_in[2];
    const float* W_off  = (const float*)d_in[3];
    const float* b_off  = (const float*)d_in[4];
    const float* W_attn = (const float*)d_in[5];
    const float* b_attn = (const float*)d_in[6];
    const float* W_out  = (const float*)d_in[7];
    const float* b_out  = (const float*)d_in[8];
    const int* batch_offsets  = (const int*)d_in[9];
    const int* spatial_shapes = (const int*)d_in[10];
    float* out = (float*)d_out;

    const int Q = in_sizes[0] / EMBED_DIM;

    float *p_off, *p_aw;
    uint32_t *p_qA, *p_midA, *p_Woff, *p_Watt, *p_Wout, *p_Vh;
    cudaGetSymbolAddress((void**)&p_off,  g_off);
    cudaGetSymbolAddress((void**)&p_aw,   g_aw);
    cudaGetSymbolAddress((void**)&p_qA,   g_qA);
    cudaGetSymbolAddress((void**)&p_midA, g_midA);
    cudaGetSymbolAddress((void**)&p_Woff, g_Woff);
    cudaGetSymbolAddress((void**)&p_Watt, g_Watt);
    cudaGetSymbolAddress((void**)&p_Wout, g_Wout);
    cudaGetSymbolAddress((void**)&p_Vh,   g_Vh);

    cudaFuncSetAttribute(gemm_packed_kernel,
                         cudaFuncAttributeMaxDynamicSharedMemorySize, GEMM_SMEM);

    // V fp32 -> fp16 (valid level regions only)
    conv_v_kernel<<<CONV_BLOCKS, 256>>>(V, p_Vh);

    // single merged prepack: query + all 3 weight matrices
    prepack_all_kernel<<<dim3(NCH, Q / 128 + 5), 128>>>(
        query, W_off, W_attn, W_out,
        p_qA, p_Woff, p_Watt, p_Wout, Q);

    // fused GEMM1: off (4 col-blocks of 64) + aw (2 col-blocks of 64)
    gemm_packed_kernel<<<dim3(6, Q / 128), 256, GEMM_SMEM>>>(
        p_qA, Q,
        p_Woff, b_off, p_off, EMBED_DIM, 4,
        p_Watt, b_attn, p_aw, 128);

    // softmax + deformable sampling (fp16 gather, corner-unrolled) -> packed mid
    msda_sample_kernel<<<Q / 2, 512>>>(
        p_off, p_aw, xyref, p_Vh, batch_offsets, spatial_shapes, p_midA, Q);

    // GEMM2: out = mid @ W_out + b_out (4 col-blocks of 64)
    gemm_packed_kernel<<<dim3(4, Q / 128), 256, GEMM_SMEM>>>(
        p_midA, Q,
        p_Wout, b_out, out, EMBED_DIM, 4,
        nullptr, nullptr, nullptr, 128);
}